// round 1
// baseline (speedup 1.0000x reference)
#include <cuda_runtime.h>
#include <math.h>

// T1DPatient dx/dt: B rows, per row: x[13], params[30], 4 scalars -> dxdt[13].
// Pure streaming / HBM-bound. SMEM-staged coalesced loads + stores.

#define TPB 256
#define PSTRIDE 31  // params row stride in smem, coprime with 32 -> conflict-free

__global__ void __launch_bounds__(TPB) t1d_dxdt_kernel(
    const float* __restrict__ gx,     // (B,13)
    const float* __restrict__ gp,     // (B,30)
    const float* __restrict__ gCHO,   // (B,)
    const float* __restrict__ gIns,   // (B,)
    const float* __restrict__ gQsto,  // (B,)
    const float* __restrict__ gFood,  // (B,)
    float* __restrict__ gout,         // (B,13)
    int B)
{
    __shared__ float sx[TPB * 13];
    __shared__ float sp[TPB * PSTRIDE];

    const int tid = threadIdx.x;
    const int rowBase = blockIdx.x * TPB;
    const int nrows = min(TPB, B - rowBase);
    const int nx = nrows * 13;
    const int np = nrows * 30;

    // ---- coalesced global -> smem ----
    const float* gxb = gx + (size_t)rowBase * 13;
    for (int j = tid; j < nx; j += TPB) sx[j] = gxb[j];

    const float* gpb = gp + (size_t)rowBase * 30;
    for (int j = tid; j < np; j += TPB) {
        int r = j / 30;
        int c = j - r * 30;
        sp[r * PSTRIDE + c] = gpb[j];
    }
    __syncthreads();

    // ---- per-thread row compute ----
    const bool active = (tid < nrows);
    float xv[13];
    float pv[30];
    if (active) {
#pragma unroll
        for (int i = 0; i < 13; i++) xv[i] = sx[tid * 13 + i];
#pragma unroll
        for (int i = 0; i < 30; i++) pv[i] = sp[tid * PSTRIDE + i];
    }
    __syncthreads();  // before reusing sx for output

    if (active) {
        const int row = rowBase + tid;
        const float CHO   = gCHO[row];
        const float ins_u = gIns[row];
        const float lQ    = gQsto[row];
        const float lF    = gFood[row];

        const float kmax = pv[0],  kmin = pv[1],  b   = pv[2],  d_  = pv[3];
        const float kabs = pv[4],  f    = pv[5],  BW  = pv[6],  kp1 = pv[7];
        const float kp2  = pv[8],  kp3  = pv[9],  Fsnc= pv[10], ke1 = pv[11];
        const float ke2  = pv[12], k1   = pv[13], k2  = pv[14], Vm0 = pv[15];
        const float Vmx  = pv[16], Km0  = pv[17], m1  = pv[18], m2  = pv[19];
        const float m4   = pv[20], m30  = pv[21], ka1 = pv[22], ka2 = pv[23];
        const float kd   = pv[24], Vi   = pv[25], p2u = pv[26], Ib  = pv[27];
        const float ki   = pv[28], ksc  = pv[29];

        const float dmg     = CHO * 1000.0f;
        const float insulin = ins_u * 6000.0f / BW;

        const float qsto = xv[0] + xv[1];
        const float Dbar = lQ + lF;
        const bool  has_food  = (Dbar > 0.0f);
        const float Dbar_safe = has_food ? Dbar : 1.0f;
        const float aa = 2.5f / ((1.0f - b) * Dbar_safe);
        const float cc = 2.5f / (d_ * Dbar_safe);
        const float kgut_eating = kmin + (kmax - kmin) * 0.5f *
            (tanhf(aa * (qsto - b * Dbar)) - tanhf(cc * (qsto - d_ * Dbar)) + 2.0f);
        const float kgut = has_food ? kgut_eating : kmax;

        float d[13];
        d[0] = -kmax * xv[0] + dmg;
        d[1] =  kmax * xv[0] - xv[1] * kgut;
        d[2] =  kgut * xv[1] - kabs * xv[2];

        const float Rat  = f * kabs * xv[2] / BW;
        const float EGPt = kp1 - kp2 * xv[3] - kp3 * xv[8];
        const float Et   = (xv[3] > ke2) ? ke1 * (xv[3] - ke2) : 0.0f;
        d[3] = (fmaxf(EGPt, 0.0f) + Rat - Fsnc - Et - k1 * xv[3] + k2 * xv[4])
               * (xv[3] >= 0.0f ? 1.0f : 0.0f);

        const float Vmt  = Vm0 + Vmx * xv[6];
        const float Uidt = Vmt * xv[4] / (Km0 + xv[4]);
        d[4] = (-Uidt + k1 * xv[3] - k2 * xv[4]) * (xv[4] >= 0.0f ? 1.0f : 0.0f);

        d[5] = (-(m2 + m4) * xv[5] + m1 * xv[9] + ka1 * xv[10] + ka2 * xv[11])
               * (xv[5] >= 0.0f ? 1.0f : 0.0f);

        const float It = xv[5] / Vi;
        d[6]  = -p2u * xv[6] + p2u * (It - Ib);
        d[7]  = -ki * (xv[7] - It);
        d[8]  = -ki * (xv[8] - xv[7]);
        d[9]  = (-(m1 + m30) * xv[9] + m2 * xv[5]) * (xv[9]  >= 0.0f ? 1.0f : 0.0f);
        d[10] = (insulin - (ka1 + kd) * xv[10])    * (xv[10] >= 0.0f ? 1.0f : 0.0f);
        d[11] = (kd * xv[10] - ka2 * xv[11])       * (xv[11] >= 0.0f ? 1.0f : 0.0f);
        d[12] = (-ksc * xv[12] + ksc * xv[3])      * (xv[12] >= 0.0f ? 1.0f : 0.0f);

#pragma unroll
        for (int i = 0; i < 13; i++) sx[tid * 13 + i] = d[i];
    }
    __syncthreads();

    // ---- coalesced smem -> global ----
    float* goutb = gout + (size_t)rowBase * 13;
    for (int j = tid; j < nx; j += TPB) goutb[j] = sx[j];
}

extern "C" void kernel_launch(void* const* d_in, const int* in_sizes, int n_in,
                              void* d_out, int out_size) {
    const float* gx    = (const float*)d_in[0];  // x (B,13)
    const float* gp    = (const float*)d_in[1];  // params (B,30)
    const float* gCHO  = (const float*)d_in[2];  // CHO (B,)
    const float* gIns  = (const float*)d_in[3];  // insulin (B,)
    const float* gQ    = (const float*)d_in[4];  // last_Qsto (B,)
    const float* gF    = (const float*)d_in[5];  // last_foodtaken (B,)
    float* gout = (float*)d_out;

    const int B = in_sizes[2];  // CHO element count = batch size
    const int grid = (B + TPB - 1) / TPB;
    t1d_dxdt_kernel<<<grid, TPB>>>(gx, gp, gCHO, gIns, gQ, gF, gout, B);
}

// round 2
// speedup vs baseline: 1.2441x; 1.2441x over previous
#include <cuda_runtime.h>
#include <math.h>

// T1DPatient dx/dt: B rows; per row x[13], params[30], 4 scalars -> dxdt[13].
// HBM-streaming kernel. float4-vectorized SMEM staging, occupancy-capped regs.

#define TPB 256
#define PSTRIDE 31  // params smem row stride, coprime with 32 -> conflict-free LDS

__global__ void __launch_bounds__(TPB, 5) t1d_dxdt_kernel(
    const float* __restrict__ gx,     // (B,13)
    const float* __restrict__ gp,     // (B,30)
    const float* __restrict__ gCHO,   // (B,)
    const float* __restrict__ gIns,   // (B,)
    const float* __restrict__ gQsto,  // (B,)
    const float* __restrict__ gFood,  // (B,)
    float* __restrict__ gout,         // (B,13)
    int B)
{
    __shared__ float4 sx4[(TPB * 13) / 4];      // 13312 B, linear layout
    __shared__ float  sp[TPB * PSTRIDE];        // 31744 B, padded layout
    float* sx = (float*)sx4;

    const int tid = threadIdx.x;
    const int rowBase = blockIdx.x * TPB;
    const int nrows = min(TPB, B - rowBase);
    const int nx  = nrows * 13;
    const int np  = nrows * 30;
    const int nx4 = nx >> 2;
    const int np4 = np >> 2;

    // ---- scalars early (overlap with staging) ----
    const bool active = (tid < nrows);
    float CHO = 0.f, ins_u = 0.f, lQ = 0.f, lF = 0.f;
    if (active) {
        const int row = rowBase + tid;
        CHO   = gCHO[row];
        ins_u = gIns[row];
        lQ    = gQsto[row];
        lF    = gFood[row];
    }

    // ---- x: vectorized global -> smem (layouts identical) ----
    const float*  gxb = gx + (size_t)rowBase * 13;
    const float4* gx4 = (const float4*)gxb;
    for (int j = tid; j < nx4; j += TPB) sx4[j] = gx4[j];
    for (int j = (nx4 << 2) + tid; j < nx; j += TPB) sx[j] = gxb[j];

    // ---- params: float4 LDG, scalar scatter into padded smem ----
    const float*  gpb = gp + (size_t)rowBase * 30;
    const float4* gp4 = (const float4*)gpb;
    for (int j = tid; j < np4; j += TPB) {
        float4 v = gp4[j];
        int g = j << 2;
        int r = g / 30;
        int c = g - 30 * r;
        float e[4] = {v.x, v.y, v.z, v.w};
#pragma unroll
        for (int k = 0; k < 4; k++) {
            sp[r * PSTRIDE + c] = e[k];
            if (++c == 30) { c = 0; r++; }
        }
    }
    for (int j = (np4 << 2) + tid; j < np; j += TPB) {
        int r = j / 30;
        int c = j - 30 * r;
        sp[r * PSTRIDE + c] = gpb[j];
    }
    __syncthreads();

    // ---- per-thread row compute; params read from smem at use ----
    float xv[13];
    if (active) {
#pragma unroll
        for (int i = 0; i < 13; i++) xv[i] = sx[tid * 13 + i];
    }
    __syncthreads();  // sx reused for output below

    if (active) {
        const float* P = sp + tid * PSTRIDE;

        const float BW   = P[6];
        const float dmg     = CHO * 1000.0f;
        const float insulin = __fdividef(ins_u * 6000.0f, BW);

        const float kmax = P[0];
        const float kmin = P[1];
        const float b    = P[2];
        const float d_   = P[3];

        const float qsto = xv[0] + xv[1];
        const float Dbar = lQ + lF;
        const bool  has_food  = (Dbar > 0.0f);
        const float Dbar_safe = has_food ? Dbar : 1.0f;
        const float aa = __fdividef(2.5f, (1.0f - b) * Dbar_safe);
        const float cc = __fdividef(2.5f, d_ * Dbar_safe);
        const float kgut_eating = kmin + (kmax - kmin) * 0.5f *
            (tanhf(aa * (qsto - b * Dbar)) - tanhf(cc * (qsto - d_ * Dbar)) + 2.0f);
        const float kgut = has_food ? kgut_eating : kmax;

        float d[13];
        const float kabs = P[4];
        d[0] = -kmax * xv[0] + dmg;
        d[1] =  kmax * xv[0] - xv[1] * kgut;
        d[2] =  kgut * xv[1] - kabs * xv[2];

        const float Rat  = __fdividef(P[5] * kabs * xv[2], BW);
        const float EGPt = P[7] - P[8] * xv[3] - P[9] * xv[8];
        const float ke1 = P[11], ke2 = P[12];
        const float Et   = (xv[3] > ke2) ? ke1 * (xv[3] - ke2) : 0.0f;
        const float k1 = P[13], k2 = P[14];
        d[3] = (fmaxf(EGPt, 0.0f) + Rat - P[10] - Et - k1 * xv[3] + k2 * xv[4])
               * (xv[3] >= 0.0f ? 1.0f : 0.0f);

        const float Vmt  = P[15] + P[16] * xv[6];
        const float Uidt = __fdividef(Vmt * xv[4], P[17] + xv[4]);
        d[4] = (-Uidt + k1 * xv[3] - k2 * xv[4]) * (xv[4] >= 0.0f ? 1.0f : 0.0f);

        const float m1 = P[18], m2 = P[19];
        const float ka1 = P[22], ka2 = P[23];
        d[5] = (-(m2 + P[20]) * xv[5] + m1 * xv[9] + ka1 * xv[10] + ka2 * xv[11])
               * (xv[5] >= 0.0f ? 1.0f : 0.0f);

        const float It = __fdividef(xv[5], P[25]);
        const float p2u = P[26];
        const float ki  = P[28];
        d[6]  = -p2u * xv[6] + p2u * (It - P[27]);
        d[7]  = -ki * (xv[7] - It);
        d[8]  = -ki * (xv[8] - xv[7]);
        d[9]  = (-(m1 + P[21]) * xv[9] + m2 * xv[5]) * (xv[9]  >= 0.0f ? 1.0f : 0.0f);
        const float kd = P[24];
        d[10] = (insulin - (ka1 + kd) * xv[10])       * (xv[10] >= 0.0f ? 1.0f : 0.0f);
        d[11] = (kd * xv[10] - ka2 * xv[11])          * (xv[11] >= 0.0f ? 1.0f : 0.0f);
        const float ksc = P[29];
        d[12] = (-ksc * xv[12] + ksc * xv[3])         * (xv[12] >= 0.0f ? 1.0f : 0.0f);

#pragma unroll
        for (int i = 0; i < 13; i++) sx[tid * 13 + i] = d[i];
    }
    __syncthreads();

    // ---- output: vectorized smem -> global ----
    float*  goutb = gout + (size_t)rowBase * 13;
    float4* go4   = (float4*)goutb;
    for (int j = tid; j < nx4; j += TPB) go4[j] = sx4[j];
    for (int j = (nx4 << 2) + tid; j < nx; j += TPB) goutb[j] = sx[j];
}

extern "C" void kernel_launch(void* const* d_in, const int* in_sizes, int n_in,
                              void* d_out, int out_size) {
    const float* gx    = (const float*)d_in[0];  // x (B,13)
    const float* gp    = (const float*)d_in[1];  // params (B,30)
    const float* gCHO  = (const float*)d_in[2];  // CHO (B,)
    const float* gIns  = (const float*)d_in[3];  // insulin (B,)
    const float* gQ    = (const float*)d_in[4];  // last_Qsto (B,)
    const float* gF    = (const float*)d_in[5];  // last_foodtaken (B,)
    float* gout = (float*)d_out;

    const int B = in_sizes[2];  // CHO element count = batch size
    const int grid = (B + TPB - 1) / TPB;
    t1d_dxdt_kernel<<<grid, TPB>>>(gx, gp, gCHO, gIns, gQ, gF, gout, B);
}

// round 3
// speedup vs baseline: 1.6589x; 1.3333x over previous
#include <cuda_runtime.h>
#include <math.h>
#include <stdint.h>

// T1DPatient dx/dt: B rows; per row x[13], params[30], 4 scalars -> dxdt[13].
// HBM-streaming. Bulk-async (TMA 1D) tile staging: 2 bulk loads + 1 bulk store
// per block, mbarrier-completed. Flat smem layouts (x stride 13 conflict-free,
// params stride 30 = 2-way LDS conflict, acceptable).

#define TPB 256

__device__ __forceinline__ uint32_t smem_u32(const void* p) {
    return (uint32_t)__cvta_generic_to_shared(p);
}

__global__ void __launch_bounds__(TPB, 5) t1d_dxdt_kernel(
    const float* __restrict__ gx,     // (B,13)
    const float* __restrict__ gp,     // (B,30)
    const float* __restrict__ gCHO,   // (B,)
    const float* __restrict__ gIns,   // (B,)
    const float* __restrict__ gQsto,  // (B,)
    const float* __restrict__ gFood,  // (B,)
    float* __restrict__ gout,         // (B,13)
    int B)
{
    __shared__ __align__(16) float sx[TPB * 13];   // 13312 B (x, then reused for out)
    __shared__ __align__(16) float sp[TPB * 30];   // 30720 B
    __shared__ __align__(8)  uint64_t mbar;

    const int tid = threadIdx.x;
    const int rowBase = blockIdx.x * TPB;
    const int nrows = min(TPB, B - rowBase);
    const int nx = nrows * 13;
    const int np = nrows * 30;

    const float* gxb  = gx + (size_t)rowBase * 13;
    const float* gpb  = gp + (size_t)rowBase * 30;
    float* goutb      = gout + (size_t)rowBase * 13;

    const bool bulk_ok = ((nrows & 3) == 0);   // 16B-multiple transfer sizes

    const uint32_t mbar_a = smem_u32(&mbar);
    if (bulk_ok) {
        if (tid == 0) {
            asm volatile("mbarrier.init.shared.b64 [%0], %1;"
                         :: "r"(mbar_a), "r"(1u));
        }
        __syncthreads();
        if (tid == 0) {
            const uint32_t bytes_x = (uint32_t)(nx * 4);
            const uint32_t bytes_p = (uint32_t)(np * 4);
            asm volatile("mbarrier.arrive.expect_tx.shared.b64 _, [%0], %1;"
                         :: "r"(mbar_a), "r"(bytes_x + bytes_p) : "memory");
            asm volatile("cp.async.bulk.shared::cta.global.mbarrier::complete_tx::bytes "
                         "[%0], [%1], %2, [%3];"
                         :: "r"(smem_u32(sx)), "l"(gxb), "r"(bytes_x), "r"(mbar_a)
                         : "memory");
            asm volatile("cp.async.bulk.shared::cta.global.mbarrier::complete_tx::bytes "
                         "[%0], [%1], %2, [%3];"
                         :: "r"(smem_u32(sp)), "l"(gpb), "r"(bytes_p), "r"(mbar_a)
                         : "memory");
        }
    } else {
        // tail-safety fallback: scalar staged copies
        for (int j = tid; j < nx; j += TPB) sx[j] = gxb[j];
        for (int j = tid; j < np; j += TPB) sp[j] = gpb[j];
        __syncthreads();
    }

    // per-row scalars: issue while TMA burst is in flight
    const bool active = (tid < nrows);
    float CHO = 0.f, ins_u = 0.f, lQ = 0.f, lF = 0.f;
    if (active) {
        const int row = rowBase + tid;
        CHO   = gCHO[row];
        ins_u = gIns[row];
        lQ    = gQsto[row];
        lF    = gFood[row];
    }

    if (bulk_ok) {
        uint32_t done;
        do {
            asm volatile("{\n\t.reg .pred p;\n\t"
                         "mbarrier.try_wait.parity.shared.b64 p, [%1], %2;\n\t"
                         "selp.b32 %0, 1, 0, p;\n\t}"
                         : "=r"(done) : "r"(mbar_a), "r"(0u) : "memory");
        } while (!done);
    }

    if (active) {
        const float* X = sx + tid * 13;   // stride 13: conflict-free
        const float* P = sp + tid * 30;   // stride 30: 2-way conflict, cheap

        float xv[13];
#pragma unroll
        for (int i = 0; i < 13; i++) xv[i] = X[i];

        const float BW      = P[6];
        const float dmg     = CHO * 1000.0f;
        const float insulin = __fdividef(ins_u * 6000.0f, BW);

        const float kmax = P[0], kmin = P[1], b = P[2], d_ = P[3];

        const float qsto = xv[0] + xv[1];
        const float Dbar = lQ + lF;
        const bool  has_food  = (Dbar > 0.0f);
        const float Dbar_safe = has_food ? Dbar : 1.0f;
        const float aa = __fdividef(2.5f, (1.0f - b) * Dbar_safe);
        const float cc = __fdividef(2.5f, d_ * Dbar_safe);
        const float kgut_eating = kmin + (kmax - kmin) * 0.5f *
            (tanhf(aa * (qsto - b * Dbar)) - tanhf(cc * (qsto - d_ * Dbar)) + 2.0f);
        const float kgut = has_food ? kgut_eating : kmax;

        float d[13];
        const float kabs = P[4];
        d[0] = -kmax * xv[0] + dmg;
        d[1] =  kmax * xv[0] - xv[1] * kgut;
        d[2] =  kgut * xv[1] - kabs * xv[2];

        const float Rat  = __fdividef(P[5] * kabs * xv[2], BW);
        const float EGPt = P[7] - P[8] * xv[3] - P[9] * xv[8];
        const float ke1 = P[11], ke2 = P[12];
        const float Et  = (xv[3] > ke2) ? ke1 * (xv[3] - ke2) : 0.0f;
        const float k1 = P[13], k2 = P[14];
        d[3] = (fmaxf(EGPt, 0.0f) + Rat - P[10] - Et - k1 * xv[3] + k2 * xv[4])
               * (xv[3] >= 0.0f ? 1.0f : 0.0f);

        const float Vmt  = P[15] + P[16] * xv[6];
        const float Uidt = __fdividef(Vmt * xv[4], P[17] + xv[4]);
        d[4] = (-Uidt + k1 * xv[3] - k2 * xv[4]) * (xv[4] >= 0.0f ? 1.0f : 0.0f);

        const float m1 = P[18], m2 = P[19];
        const float ka1 = P[22], ka2 = P[23];
        d[5] = (-(m2 + P[20]) * xv[5] + m1 * xv[9] + ka1 * xv[10] + ka2 * xv[11])
               * (xv[5] >= 0.0f ? 1.0f : 0.0f);

        const float It  = __fdividef(xv[5], P[25]);
        const float p2u = P[26];
        const float ki  = P[28];
        d[6]  = -p2u * xv[6] + p2u * (It - P[27]);
        d[7]  = -ki * (xv[7] - It);
        d[8]  = -ki * (xv[8] - xv[7]);
        d[9]  = (-(m1 + P[21]) * xv[9] + m2 * xv[5]) * (xv[9]  >= 0.0f ? 1.0f : 0.0f);
        const float kd = P[24];
        d[10] = (insulin - (ka1 + kd) * xv[10])      * (xv[10] >= 0.0f ? 1.0f : 0.0f);
        d[11] = (kd * xv[10] - ka2 * xv[11])         * (xv[11] >= 0.0f ? 1.0f : 0.0f);
        const float ksc = P[29];
        d[12] = (-ksc * xv[12] + ksc * xv[3])        * (xv[12] >= 0.0f ? 1.0f : 0.0f);

        // each thread overwrites exactly the row it read: no barrier needed
        float* O = sx + tid * 13;
#pragma unroll
        for (int i = 0; i < 13; i++) O[i] = d[i];
    }
    __syncthreads();

    if (bulk_ok) {
        asm volatile("fence.proxy.async.shared::cta;" ::: "memory");
        if (tid == 0) {
            const uint32_t bytes_x = (uint32_t)(nx * 4);
            asm volatile("cp.async.bulk.global.shared::cta.bulk_group "
                         "[%0], [%1], %2;"
                         :: "l"(goutb), "r"(smem_u32(sx)), "r"(bytes_x)
                         : "memory");
            asm volatile("cp.async.bulk.commit_group;" ::: "memory");
            asm volatile("cp.async.bulk.wait_group 0;" ::: "memory");
        }
    } else {
        for (int j = tid; j < nx; j += TPB) goutb[j] = sx[j];
    }
}

extern "C" void kernel_launch(void* const* d_in, const int* in_sizes, int n_in,
                              void* d_out, int out_size) {
    const float* gx    = (const float*)d_in[0];  // x (B,13)
    const float* gp    = (const float*)d_in[1];  // params (B,30)
    const float* gCHO  = (const float*)d_in[2];  // CHO (B,)
    const float* gIns  = (const float*)d_in[3];  // insulin (B,)
    const float* gQ    = (const float*)d_in[4];  // last_Qsto (B,)
    const float* gF    = (const float*)d_in[5];  // last_foodtaken (B,)
    float* gout = (float*)d_out;

    const int B = in_sizes[2];  // CHO element count = batch size
    const int grid = (B + TPB - 1) / TPB;
    t1d_dxdt_kernel<<<grid, TPB>>>(gx, gp, gCHO, gIns, gQ, gF, gout, B);
}